// round 4
// baseline (speedup 1.0000x reference)
#include <cuda_runtime.h>

#define BB 128
#define NN 4096
#define SD 448
#define NCH 16

__device__ float g_slots[BB * SD];
__device__ float g_qk[BB * SD];
__device__ float g_part[BB * NCH * SD];
__device__ float g_pden[BB * NCH * 7];

typedef unsigned long long ull;

__device__ __forceinline__ void fma2(ull& c, ull a, ull b) {
    asm("fma.rn.f32x2 %0, %1, %2, %0;" : "+l"(c) : "l"(a), "l"(b));
}
__device__ __forceinline__ ull pk2(float x, float y) {
    ull r; asm("mov.b64 %0, {%1, %2};" : "=l"(r) : "f"(x), "f"(y)); return r;
}
__device__ __forceinline__ float2 up2(ull v) {
    float2 r; asm("mov.b64 {%0, %1}, %2;" : "=f"(r.x), "=f"(r.y) : "l"(v)); return r;
}
__device__ __forceinline__ float ex2a(float x) {
    float y; asm("ex2.approx.f32 %0, %1;" : "=f"(y) : "f"(x)); return y;
}
__device__ __forceinline__ float rcpa(float x) {
    float y; asm("rcp.approx.f32 %0, %1;" : "=f"(y) : "f"(x)); return y;
}
__device__ __forceinline__ float sigf(float x) { return 1.0f / (1.0f + __expf(-x)); }

// ======================= slots init =======================
__global__ void kinit(const float* __restrict__ nbg, const float* __restrict__ nfg,
                      const float* __restrict__ bmu, const float* __restrict__ bls,
                      const float* __restrict__ fmu, const float* __restrict__ fls) {
    int b = blockIdx.x, t = threadIdx.x, s = t >> 6, d = t & 63;
    float val;
    if (s == 0) val = bmu[d] + expf(bls[d]) * nbg[b * 64 + d];
    else        val = fmu[d] + expf(fls[d]) * nfg[(b * 6 + (s - 1)) * 64 + d];
    g_slots[b * SD + t] = val;
}

// ======== s=LN(slots); q = s@Wq^T; qk = C * (q @ Wk) ========
__global__ __launch_bounds__(448) void kq(const float* __restrict__ Wq,
                                          const float* __restrict__ Wk,
                                          const float* __restrict__ lg,
                                          const float* __restrict__ lb) {
    __shared__ __align__(16) float sn[7][64], sq[7][64];
    __shared__ float s_red[14][2];
    int b = blockIdx.x, t = threadIdx.x, s = t >> 6, d = t & 63;
    int w = t >> 5;
    float val = g_slots[b * SD + t];
    float s1 = val, s2 = val * val;
#pragma unroll
    for (int off = 16; off; off >>= 1) {
        s1 += __shfl_xor_sync(0xffffffffu, s1, off);
        s2 += __shfl_xor_sync(0xffffffffu, s2, off);
    }
    if ((t & 31) == 0) { s_red[w][0] = s1; s_red[w][1] = s2; }
    __syncthreads();
    float tot  = s_red[2 * s][0] + s_red[2 * s + 1][0];
    float tot2 = s_red[2 * s][1] + s_red[2 * s + 1][1];
    float mu = tot * (1.0f / 64.0f);
    float rs = rsqrtf(tot2 * (1.0f / 64.0f) - mu * mu + 1e-5f);
    sn[s][d] = fmaf((val - mu) * rs, lg[d], lb[d]);
    __syncthreads();
    float acc = 0.f;
    const float4* wr = (const float4*)(Wq + d * 64);
    const float4* xr = (const float4*)sn[s];
#pragma unroll
    for (int i = 0; i < 16; i++) {
        float4 a = xr[i], wv = __ldg(wr + i);
        acc = fmaf(a.x, wv.x, acc); acc = fmaf(a.y, wv.y, acc);
        acc = fmaf(a.z, wv.z, acc); acc = fmaf(a.w, wv.w, acc);
    }
    sq[s][d] = acc;
    __syncthreads();
    float kacc = 0.f;
#pragma unroll 8
    for (int e = 0; e < 64; e++) kacc = fmaf(sq[s][e], __ldg(Wk + e * 64 + d), kacc);
    g_qk[b * SD + t] = kacc * 0.18033688011112042f;  // D^-0.5 * log2(e)
}

// ===== fused LN(inputs) -> logits -> softmax(+eps) -> U/den partials =====
__global__ __launch_bounds__(256) void kattn(const float* __restrict__ x,
                                             const float* __restrict__ lg,
                                             const float* __restrict__ lb) {
    __shared__ __align__(16) float s_qk[7][64];
    __shared__ float s_u[8][7][64];
    __shared__ float s_d[8][7];
    int b = blockIdx.y, chunk = blockIdx.x;
    int tid = threadIdx.x, warp = tid >> 5, lane = tid & 31;
    int grp = lane >> 3, sub = lane & 7, d0 = sub << 3;

    for (int i = tid; i < SD; i += 256)
        ((float*)s_qk)[i] = g_qk[b * SD + i];

    float lng[8], lnb[8];
#pragma unroll
    for (int j = 0; j < 8; j++) { lng[j] = lg[d0 + j]; lnb[j] = lb[d0 + j]; }

    ull U[7][4];
    float den[7];
#pragma unroll
    for (int s = 0; s < 7; s++) {
        den[s] = 0.f;
#pragma unroll
        for (int j = 0; j < 4; j++) U[s][j] = 0ull;
    }
    __syncthreads();

    const float* xp = x + ((size_t)b * NN + chunk * 256 + warp * 4 + grp) * 64 + d0;
    float4 cx0 = *(const float4*)xp;
    float4 cx1 = *(const float4*)(xp + 4);

#pragma unroll
    for (int step = 0; step < 8; step++) {
        float4 nx0 = cx0, nx1 = cx1;
        if (step < 7) {
            xp += 32 * 64;
            nx0 = *(const float4*)xp;
            nx1 = *(const float4*)(xp + 4);
        }
        float xf[8] = {cx0.x, cx0.y, cx0.z, cx0.w, cx1.x, cx1.y, cx1.z, cx1.w};
        float s1 = 0.f, s2 = 0.f;
#pragma unroll
        for (int j = 0; j < 8; j++) { s1 += xf[j]; s2 = fmaf(xf[j], xf[j], s2); }
#pragma unroll
        for (int off = 1; off <= 4; off <<= 1) {
            s1 += __shfl_xor_sync(0xffffffffu, s1, off);
            s2 += __shfl_xor_sync(0xffffffffu, s2, off);
        }
        float mu = s1 * (1.0f / 64.0f);
        float rs = rsqrtf(s2 * (1.0f / 64.0f) - mu * mu + 1e-5f);
        ull p[4];
#pragma unroll
        for (int j = 0; j < 4; j++) {
            float a0 = fmaf((xf[2 * j]     - mu) * rs, lng[2 * j],     lnb[2 * j]);
            float a1 = fmaf((xf[2 * j + 1] - mu) * rs, lng[2 * j + 1], lnb[2 * j + 1]);
            p[j] = pk2(a0, a1);
        }
        float l[7];
#pragma unroll
        for (int s = 0; s < 7; s++) {
            const ull* qrow = (const ull*)&s_qk[s][d0];
            ull acc = 0ull;
            fma2(acc, p[0], qrow[0]); fma2(acc, p[1], qrow[1]);
            fma2(acc, p[2], qrow[2]); fma2(acc, p[3], qrow[3]);
            float2 pf = up2(acc);
            l[s] = pf.x + pf.y;
        }
#pragma unroll
        for (int off = 1; off <= 4; off <<= 1)
#pragma unroll
            for (int s = 0; s < 7; s++)
                l[s] += __shfl_xor_sync(0xffffffffu, l[s], off);
        float m = l[0];
#pragma unroll
        for (int s = 1; s < 7; s++) m = fmaxf(m, l[s]);
        float e[7], ws = 0.f;
#pragma unroll
        for (int s = 0; s < 7; s++) { e[s] = ex2a(l[s] - m); ws += e[s]; }
        float rinv = rcpa(ws);
#pragma unroll
        for (int s = 0; s < 7; s++) {
            float wv = fmaf(e[s], rinv, 1e-8f);
            den[s] += wv;
            ull wp = pk2(wv, wv);
            fma2(U[s][0], wp, p[0]); fma2(U[s][1], wp, p[1]);
            fma2(U[s][2], wp, p[2]); fma2(U[s][3], wp, p[3]);
        }
        cx0 = nx0; cx1 = nx1;
    }

    // reduce across the 4 groups of each warp
    float u[7][8];
#pragma unroll
    for (int s = 0; s < 7; s++)
#pragma unroll
        for (int j = 0; j < 4; j++) {
            float2 t2 = up2(U[s][j]);
            u[s][2 * j] = t2.x; u[s][2 * j + 1] = t2.y;
        }
#pragma unroll
    for (int off = 8; off <= 16; off <<= 1) {
#pragma unroll
        for (int s = 0; s < 7; s++) {
#pragma unroll
            for (int j = 0; j < 8; j++)
                u[s][j] += __shfl_xor_sync(0xffffffffu, u[s][j], off);
            den[s] += __shfl_xor_sync(0xffffffffu, den[s], off);
        }
    }
    if (lane < 8) {
#pragma unroll
        for (int s = 0; s < 7; s++)
#pragma unroll
            for (int j = 0; j < 8; j++)
                s_u[warp][s][lane * 8 + j] = u[s][j];
    }
    if (lane == 0)
#pragma unroll
        for (int s = 0; s < 7; s++) s_d[warp][s] = den[s];
    __syncthreads();

    float* outp = g_part + (size_t)(b * NCH + chunk) * SD;
    for (int idx = tid; idx < SD; idx += 256) {
        int s = idx >> 6, d = idx & 63;
        float a = 0.f;
#pragma unroll
        for (int w8 = 0; w8 < 8; w8++) a += s_u[w8][s][d];
        outp[idx] = a;
    }
    if (tid < 7) {
        float a = 0.f;
#pragma unroll
        for (int w8 = 0; w8 < 8; w8++) a += s_d[w8][tid];
        g_pden[(b * NCH + chunk) * 7 + tid] = a;
    }
}

// ===== reduce partials -> updates = (U/den)@Wv^T -> GRU -> LN -> MLP =====
__global__ __launch_bounds__(448) void kupdate(
    const float* __restrict__ Wv, const float* __restrict__ W_ih,
    const float* __restrict__ W_hh, const float* __restrict__ b_ih,
    const float* __restrict__ b_hh, const float* __restrict__ w1,
    const float* __restrict__ b1, const float* __restrict__ w2,
    const float* __restrict__ b2, const float* __restrict__ lg,
    const float* __restrict__ lb, float* __restrict__ out, int last) {
    __shared__ __align__(16) float sU[7][64], s_upd[7][64], s_prev[7][64],
                                   s_m[7][64], s_hid[7][128];
    __shared__ float s_red[14][2], s_rden[7];
    int b = blockIdx.x, t = threadIdx.x, s = t >> 6, d = t & 63, w = t >> 5;

    float num = 0.f;
    const float* pp = g_part + (size_t)b * NCH * SD + t;
#pragma unroll
    for (int c = 0; c < NCH; c++) num += pp[c * SD];
    if (t < 7) {
        float dn = 0.f;
        const float* dp = g_pden + b * NCH * 7 + t;
#pragma unroll
        for (int c = 0; c < NCH; c++) dn += dp[c * 7];
        s_rden[t] = 1.0f / dn;
    }
    float prev = g_slots[b * SD + t];
    s_prev[s][d] = prev;
    __syncthreads();
    sU[s][d] = num * s_rden[s];
    __syncthreads();

    float acc = 0.f;
    {
        const float4* wv4 = (const float4*)(Wv + d * 64);
        const float4* u4 = (const float4*)sU[s];
#pragma unroll
        for (int i = 0; i < 16; i++) {
            float4 a = u4[i], wv = __ldg(wv4 + i);
            acc = fmaf(a.x, wv.x, acc); acc = fmaf(a.y, wv.y, acc);
            acc = fmaf(a.z, wv.z, acc); acc = fmaf(a.w, wv.w, acc);
        }
    }
    s_upd[s][d] = acc;
    __syncthreads();

    float gi0 = b_ih[d], gi1 = b_ih[64 + d], gi2 = b_ih[128 + d];
    float gh0 = b_hh[d], gh1 = b_hh[64 + d], gh2 = b_hh[128 + d];
    {
        const float4* up = (const float4*)s_upd[s];
        const float4* hp = (const float4*)s_prev[s];
        const float4* wi0 = (const float4*)(W_ih + d * 64);
        const float4* wi1 = (const float4*)(W_ih + (64 + d) * 64);
        const float4* wi2 = (const float4*)(W_ih + (128 + d) * 64);
        const float4* wh0 = (const float4*)(W_hh + d * 64);
        const float4* wh1 = (const float4*)(W_hh + (64 + d) * 64);
        const float4* wh2 = (const float4*)(W_hh + (128 + d) * 64);
#pragma unroll
        for (int i = 0; i < 16; i++) {
            float4 uu = up[i], hh = hp[i];
            float4 a;
            a = __ldg(wi0 + i);
            gi0 = fmaf(uu.x, a.x, gi0); gi0 = fmaf(uu.y, a.y, gi0);
            gi0 = fmaf(uu.z, a.z, gi0); gi0 = fmaf(uu.w, a.w, gi0);
            a = __ldg(wi1 + i);
            gi1 = fmaf(uu.x, a.x, gi1); gi1 = fmaf(uu.y, a.y, gi1);
            gi1 = fmaf(uu.z, a.z, gi1); gi1 = fmaf(uu.w, a.w, gi1);
            a = __ldg(wi2 + i);
            gi2 = fmaf(uu.x, a.x, gi2); gi2 = fmaf(uu.y, a.y, gi2);
            gi2 = fmaf(uu.z, a.z, gi2); gi2 = fmaf(uu.w, a.w, gi2);
            a = __ldg(wh0 + i);
            gh0 = fmaf(hh.x, a.x, gh0); gh0 = fmaf(hh.y, a.y, gh0);
            gh0 = fmaf(hh.z, a.z, gh0); gh0 = fmaf(hh.w, a.w, gh0);
            a = __ldg(wh1 + i);
            gh1 = fmaf(hh.x, a.x, gh1); gh1 = fmaf(hh.y, a.y, gh1);
            gh1 = fmaf(hh.z, a.z, gh1); gh1 = fmaf(hh.w, a.w, gh1);
            a = __ldg(wh2 + i);
            gh2 = fmaf(hh.x, a.x, gh2); gh2 = fmaf(hh.y, a.y, gh2);
            gh2 = fmaf(hh.z, a.z, gh2); gh2 = fmaf(hh.w, a.w, gh2);
        }
    }
    float r = sigf(gi0 + gh0);
    float z = sigf(gi1 + gh1);
    float n = tanhf(gi2 + r * gh2);
    float h = (1.0f - z) * n + z * prev;

    float s1 = h, s2 = h * h;
#pragma unroll
    for (int off = 16; off; off >>= 1) {
        s1 += __shfl_xor_sync(0xffffffffu, s1, off);
        s2 += __shfl_xor_sync(0xffffffffu, s2, off);
    }
    if ((t & 31) == 0) { s_red[w][0] = s1; s_red[w][1] = s2; }
    __syncthreads();
    float tot  = s_red[2 * s][0] + s_red[2 * s + 1][0];
    float tot2 = s_red[2 * s][1] + s_red[2 * s + 1][1];
    float mu = tot * (1.0f / 64.0f);
    float rs = rsqrtf(tot2 * (1.0f / 64.0f) - mu * mu + 1e-5f);
    s_m[s][d] = fmaf((h - mu) * rs, lg[d], lb[d]);
    __syncthreads();

    float h0 = b1[d], h1 = b1[64 + d];
    {
        const float4* mp = (const float4*)s_m[s];
        const float4* wa = (const float4*)(w1 + d * 64);
        const float4* wb = (const float4*)(w1 + (64 + d) * 64);
#pragma unroll
        for (int i = 0; i < 16; i++) {
            float4 mm = mp[i];
            float4 a = __ldg(wa + i);
            h0 = fmaf(mm.x, a.x, h0); h0 = fmaf(mm.y, a.y, h0);
            h0 = fmaf(mm.z, a.z, h0); h0 = fmaf(mm.w, a.w, h0);
            a = __ldg(wb + i);
            h1 = fmaf(mm.x, a.x, h1); h1 = fmaf(mm.y, a.y, h1);
            h1 = fmaf(mm.z, a.z, h1); h1 = fmaf(mm.w, a.w, h1);
        }
    }
    s_hid[s][d] = fmaxf(h0, 0.f);
    s_hid[s][64 + d] = fmaxf(h1, 0.f);
    __syncthreads();

    float mo = b2[d];
    {
        const float4* hid4 = (const float4*)s_hid[s];
        const float4* w24 = (const float4*)(w2 + d * 128);
#pragma unroll
        for (int i = 0; i < 32; i++) {
            float4 hh = hid4[i], a = __ldg(w24 + i);
            mo = fmaf(hh.x, a.x, mo); mo = fmaf(hh.y, a.y, mo);
            mo = fmaf(hh.z, a.z, mo); mo = fmaf(hh.w, a.w, mo);
        }
    }
    float res = h + mo;
    g_slots[b * SD + t] = res;
    if (last) out[b * SD + t] = res;
}

extern "C" void kernel_launch(void* const* d_in, const int* in_sizes, int n_in,
                              void* d_out, int out_size) {
    const float* inputs = (const float*)d_in[0];
    const float* nbg    = (const float*)d_in[1];
    const float* nfg    = (const float*)d_in[2];
    const float* lin_g  = (const float*)d_in[3];
    const float* lin_b  = (const float*)d_in[4];
    const float* lsl_g  = (const float*)d_in[5];
    const float* lsl_b  = (const float*)d_in[6];
    const float* lml_g  = (const float*)d_in[7];
    const float* lml_b  = (const float*)d_in[8];
    const float* Wq     = (const float*)d_in[9];
    const float* Wk     = (const float*)d_in[10];
    const float* Wv     = (const float*)d_in[11];
    const float* W_ih   = (const float*)d_in[12];
    const float* W_hh   = (const float*)d_in[13];
    const float* b_ih   = (const float*)d_in[14];
    const float* b_hh   = (const float*)d_in[15];
    const float* w1     = (const float*)d_in[16];
    const float* b1     = (const float*)d_in[17];
    const float* w2     = (const float*)d_in[18];
    const float* b2     = (const float*)d_in[19];
    const float* bmu    = (const float*)d_in[20];
    const float* bls    = (const float*)d_in[21];
    const float* fmu    = (const float*)d_in[22];
    const float* fls    = (const float*)d_in[23];
    float* out = (float*)d_out;

    kinit<<<BB, SD>>>(nbg, nfg, bmu, bls, fmu, fls);
    for (int it = 0; it < 3; it++) {
        kq<<<BB, SD>>>(Wq, Wk, lsl_g, lsl_b);
        dim3 ga(NCH, BB);
        kattn<<<ga, 256>>>(inputs, lin_g, lin_b);
        kupdate<<<BB, SD>>>(Wv, W_ih, W_hh, b_ih, b_hh, w1, b1, w2, b2,
                            lml_g, lml_b, out, it == 2);
    }
}

// round 6
// speedup vs baseline: 1.2234x; 1.2234x over previous
#include <cuda_runtime.h>

#define BB 128
#define NN 4096
#define SD 448
#define NCH 16

__device__ float g_slots[BB * SD];
__device__ float g_qk[BB * SD];
__device__ float g_part[BB * NCH * SD];
__device__ float g_pden[BB * NCH * 7];
__device__ float g_M[64 * 64];

typedef unsigned long long ull;

__device__ __forceinline__ void fma2(ull& c, ull a, ull b) {
    asm("fma.rn.f32x2 %0, %1, %2, %0;" : "+l"(c) : "l"(a), "l"(b));
}
__device__ __forceinline__ ull pk2(float x, float y) {
    ull r; asm("mov.b64 %0, {%1, %2};" : "=l"(r) : "f"(x), "f"(y)); return r;
}
__device__ __forceinline__ float2 up2(ull v) {
    float2 r; asm("mov.b64 {%0, %1}, %2;" : "=f"(r.x), "=f"(r.y) : "l"(v)); return r;
}
__device__ __forceinline__ float ex2a(float x) {
    float y; asm("ex2.approx.f32 %0, %1;" : "=f"(y) : "f"(x)); return y;
}
__device__ __forceinline__ float rcpa(float x) {
    float y; asm("rcp.approx.f32 %0, %1;" : "=f"(y) : "f"(x)); return y;
}
__device__ __forceinline__ float sigf(float x) { return 1.0f / (1.0f + __expf(-x)); }

// ================= kprep: M = C * Wq^T @ Wk (once) =================
__global__ void kprep(const float* __restrict__ Wq, const float* __restrict__ Wk) {
    int e = blockIdx.x, d = threadIdx.x;
    float acc = 0.f;
#pragma unroll 16
    for (int j = 0; j < 64; j++)
        acc = fmaf(Wq[j * 64 + e], Wk[j * 64 + d], acc);
    g_M[e * 64 + d] = acc * 0.18033688011112042f;  // D^-0.5 * log2(e)
}

// ====== kinitq: slots init + LN(slots) + qk = sn @ M ======
__global__ __launch_bounds__(448) void kinitq(
    const float* __restrict__ nbg, const float* __restrict__ nfg,
    const float* __restrict__ bmu, const float* __restrict__ bls,
    const float* __restrict__ fmu, const float* __restrict__ fls,
    const float* __restrict__ lg, const float* __restrict__ lb) {
    __shared__ __align__(16) float sn[7][64];
    __shared__ float s_red[14][2];
    int b = blockIdx.x, t = threadIdx.x, s = t >> 6, d = t & 63, w = t >> 5;
    float val;
    if (s == 0) val = bmu[d] + expf(bls[d]) * nbg[b * 64 + d];
    else        val = fmu[d] + expf(fls[d]) * nfg[(b * 6 + (s - 1)) * 64 + d];
    g_slots[b * SD + t] = val;

    float s1 = val, s2 = val * val;
#pragma unroll
    for (int off = 16; off; off >>= 1) {
        s1 += __shfl_xor_sync(0xffffffffu, s1, off);
        s2 += __shfl_xor_sync(0xffffffffu, s2, off);
    }
    if ((t & 31) == 0) { s_red[w][0] = s1; s_red[w][1] = s2; }
    __syncthreads();
    float tot  = s_red[2 * s][0] + s_red[2 * s + 1][0];
    float tot2 = s_red[2 * s][1] + s_red[2 * s + 1][1];
    float mu = tot * (1.0f / 64.0f);
    float rs = rsqrtf(tot2 * (1.0f / 64.0f) - mu * mu + 1e-5f);
    sn[s][d] = fmaf((val - mu) * rs, lg[d], lb[d]);
    __syncthreads();

    float acc = 0.f;
    const float4* sn4 = (const float4*)sn[s];
#pragma unroll
    for (int i = 0; i < 16; i++) {
        float4 x = sn4[i];
        float m0 = g_M[(4 * i + 0) * 64 + d], m1 = g_M[(4 * i + 1) * 64 + d];
        float m2 = g_M[(4 * i + 2) * 64 + d], m3 = g_M[(4 * i + 3) * 64 + d];
        acc = fmaf(x.x, m0, acc); acc = fmaf(x.y, m1, acc);
        acc = fmaf(x.z, m2, acc); acc = fmaf(x.w, m3, acc);
    }
    g_qk[b * SD + t] = acc;
}

// ===== kattn: fused LN(inputs) -> logits -> softmax(+eps) -> U/den partials =====
__global__ __launch_bounds__(256) void kattn(const float* __restrict__ x,
                                             const float* __restrict__ lg,
                                             const float* __restrict__ lb) {
    __shared__ __align__(16) float s_qk[7][64];
    __shared__ float s_u[8][7][64];
    __shared__ float s_d[8][7];
    int b = blockIdx.y, chunk = blockIdx.x;
    int tid = threadIdx.x, warp = tid >> 5, lane = tid & 31;
    int grp = lane >> 3, sub = lane & 7, d0 = sub << 3;

    for (int i = tid; i < SD; i += 256)
        ((float*)s_qk)[i] = g_qk[b * SD + i];

    float lng[8], lnb[8];
#pragma unroll
    for (int j = 0; j < 8; j++) { lng[j] = lg[d0 + j]; lnb[j] = lb[d0 + j]; }

    ull U[7][4];
    float den[7];
#pragma unroll
    for (int s = 0; s < 7; s++) {
        den[s] = 0.f;
#pragma unroll
        for (int j = 0; j < 4; j++) U[s][j] = 0ull;
    }
    __syncthreads();

    const float* xp = x + ((size_t)b * NN + chunk * 256 + warp * 4 + grp) * 64 + d0;
    float4 cx0 = *(const float4*)xp;
    float4 cx1 = *(const float4*)(xp + 4);

#pragma unroll
    for (int step = 0; step < 8; step++) {
        float4 nx0 = cx0, nx1 = cx1;
        if (step < 7) {
            xp += 32 * 64;
            nx0 = *(const float4*)xp;
            nx1 = *(const float4*)(xp + 4);
        }
        float xf[8] = {cx0.x, cx0.y, cx0.z, cx0.w, cx1.x, cx1.y, cx1.z, cx1.w};
        float s1 = 0.f, s2 = 0.f;
#pragma unroll
        for (int j = 0; j < 8; j++) { s1 += xf[j]; s2 = fmaf(xf[j], xf[j], s2); }
#pragma unroll
        for (int off = 1; off <= 4; off <<= 1) {
            s1 += __shfl_xor_sync(0xffffffffu, s1, off);
            s2 += __shfl_xor_sync(0xffffffffu, s2, off);
        }
        float mu = s1 * (1.0f / 64.0f);
        float rs = rsqrtf(s2 * (1.0f / 64.0f) - mu * mu + 1e-5f);
        ull p[4];
#pragma unroll
        for (int j = 0; j < 4; j++) {
            float a0 = fmaf((xf[2 * j]     - mu) * rs, lng[2 * j],     lnb[2 * j]);
            float a1 = fmaf((xf[2 * j + 1] - mu) * rs, lng[2 * j + 1], lnb[2 * j + 1]);
            p[j] = pk2(a0, a1);
        }
        float l[7];
#pragma unroll
        for (int s = 0; s < 7; s++) {
            const ull* qrow = (const ull*)&s_qk[s][d0];
            ull acc = 0ull;
            fma2(acc, p[0], qrow[0]); fma2(acc, p[1], qrow[1]);
            fma2(acc, p[2], qrow[2]); fma2(acc, p[3], qrow[3]);
            float2 pf = up2(acc);
            l[s] = pf.x + pf.y;
        }
#pragma unroll
        for (int off = 1; off <= 4; off <<= 1)
#pragma unroll
            for (int s = 0; s < 7; s++)
                l[s] += __shfl_xor_sync(0xffffffffu, l[s], off);
        float m = l[0];
#pragma unroll
        for (int s = 1; s < 7; s++) m = fmaxf(m, l[s]);
        float e[7], ws = 0.f;
#pragma unroll
        for (int s = 0; s < 7; s++) { e[s] = ex2a(l[s] - m); ws += e[s]; }
        float rinv = rcpa(ws);
#pragma unroll
        for (int s = 0; s < 7; s++) {
            float wv = fmaf(e[s], rinv, 1e-8f);
            den[s] += wv;
            ull wp = pk2(wv, wv);
            fma2(U[s][0], wp, p[0]); fma2(U[s][1], wp, p[1]);
            fma2(U[s][2], wp, p[2]); fma2(U[s][3], wp, p[3]);
        }
        cx0 = nx0; cx1 = nx1;
    }

    float u[7][8];
#pragma unroll
    for (int s = 0; s < 7; s++)
#pragma unroll
        for (int j = 0; j < 4; j++) {
            float2 t2 = up2(U[s][j]);
            u[s][2 * j] = t2.x; u[s][2 * j + 1] = t2.y;
        }
#pragma unroll
    for (int off = 8; off <= 16; off <<= 1) {
#pragma unroll
        for (int s = 0; s < 7; s++) {
#pragma unroll
            for (int j = 0; j < 8; j++)
                u[s][j] += __shfl_xor_sync(0xffffffffu, u[s][j], off);
            den[s] += __shfl_xor_sync(0xffffffffu, den[s], off);
        }
    }
    if (lane < 8) {
#pragma unroll
        for (int s = 0; s < 7; s++)
#pragma unroll
            for (int j = 0; j < 8; j++)
                s_u[warp][s][lane * 8 + j] = u[s][j];
    }
    if (lane == 0)
#pragma unroll
        for (int s = 0; s < 7; s++) s_d[warp][s] = den[s];
    __syncthreads();

    float* outp = g_part + (size_t)(b * NCH + chunk) * SD;
    for (int idx = tid; idx < SD; idx += 256) {
        int s = idx >> 6, d = idx & 63;
        float a = 0.f;
#pragma unroll
        for (int w8 = 0; w8 < 8; w8++) a += s_u[w8][s][d];
        outp[idx] = a;
    }
    if (tid < 7) {
        float a = 0.f;
#pragma unroll
        for (int w8 = 0; w8 < 8; w8++) a += s_d[w8][tid];
        g_pden[(b * NCH + chunk) * 7 + tid] = a;
    }
}

// ===== kupd: partial-reduce -> Wv -> GRU -> LN -> MLP -> (next qk) =====
// 64 threads per batch; all 7 slots register-blocked per thread.
__global__ __launch_bounds__(64) void kupd(
    const float* __restrict__ Wv, const float* __restrict__ W_ih,
    const float* __restrict__ W_hh, const float* __restrict__ b_ih,
    const float* __restrict__ b_hh, const float* __restrict__ w1,
    const float* __restrict__ b1p, const float* __restrict__ w2,
    const float* __restrict__ b2p, const float* __restrict__ lmg,
    const float* __restrict__ lmb, const float* __restrict__ lsg,
    const float* __restrict__ lsb, float* __restrict__ out, int last) {
    __shared__ __align__(16) float sU[7][64], sPrev[7][64], sUpd[7][64],
                                   sM_[7][64], sHid[7][128];
    __shared__ float s_red[2][7][2], s_rden[7];
    int b = blockIdx.x, d = threadIdx.x;
    int lane = d & 31, w = d >> 5;

    // ---- P0: reduce partials ----
    float num[7];
#pragma unroll
    for (int s = 0; s < 7; s++) num[s] = 0.f;
    const float* pp = g_part + (size_t)b * NCH * SD + d;
#pragma unroll
    for (int c = 0; c < NCH; c++) {
        const float* q = pp + c * SD;
#pragma unroll
        for (int s = 0; s < 7; s++) num[s] += q[s * 64];
    }
    if (d < 7) {
        float dn = 0.f;
        const float* dp = g_pden + b * NCH * 7 + d;
#pragma unroll
        for (int c = 0; c < NCH; c++) dn += dp[c * 7];
        s_rden[d] = 1.0f / dn;
    }
    float prev[7];
#pragma unroll
    for (int s = 0; s < 7; s++) {
        prev[s] = g_slots[b * SD + s * 64 + d];
        sPrev[s][d] = prev[s];
    }
    __syncthreads();
#pragma unroll
    for (int s = 0; s < 7; s++) sU[s][d] = num[s] * s_rden[s];
    __syncthreads();

    // ---- P1: upd = U @ Wv^T ----
    ull upd2[7];
#pragma unroll
    for (int s = 0; s < 7; s++) upd2[s] = 0ull;
    const ulonglong2* wv4 = (const ulonglong2*)(Wv + d * 64);
#pragma unroll
    for (int i = 0; i < 16; i++) {
        ulonglong2 wp = wv4[i];
#pragma unroll
        for (int s = 0; s < 7; s++) {
            ulonglong2 uq = ((const ulonglong2*)sU[s])[i];
            fma2(upd2[s], wp.x, uq.x); fma2(upd2[s], wp.y, uq.y);
        }
    }
#pragma unroll
    for (int s = 0; s < 7; s++) {
        float2 t = up2(upd2[s]);
        sUpd[s][d] = t.x + t.y;
    }
    __syncthreads();

    // ---- P2: GRU gates ----
    ull g2[6][7];
#pragma unroll
    for (int g = 0; g < 6; g++)
#pragma unroll
        for (int s = 0; s < 7; s++) g2[g][s] = 0ull;
    const ulonglong2* wi0 = (const ulonglong2*)(W_ih + d * 64);
    const ulonglong2* wi1 = (const ulonglong2*)(W_ih + (64 + d) * 64);
    const ulonglong2* wi2 = (const ulonglong2*)(W_ih + (128 + d) * 64);
    const ulonglong2* wh0 = (const ulonglong2*)(W_hh + d * 64);
    const ulonglong2* wh1 = (const ulonglong2*)(W_hh + (64 + d) * 64);
    const ulonglong2* wh2 = (const ulonglong2*)(W_hh + (128 + d) * 64);
#pragma unroll
    for (int i = 0; i < 16; i++) {
        ulonglong2 a0 = wi0[i], a1 = wi1[i], a2 = wi2[i];
        ulonglong2 h0 = wh0[i], h1 = wh1[i], h2 = wh2[i];
#pragma unroll
        for (int s = 0; s < 7; s++) {
            ulonglong2 uq = ((const ulonglong2*)sUpd[s])[i];
            ulonglong2 pq = ((const ulonglong2*)sPrev[s])[i];
            fma2(g2[0][s], a0.x, uq.x); fma2(g2[0][s], a0.y, uq.y);
            fma2(g2[1][s], a1.x, uq.x); fma2(g2[1][s], a1.y, uq.y);
            fma2(g2[2][s], a2.x, uq.x); fma2(g2[2][s], a2.y, uq.y);
            fma2(g2[3][s], h0.x, pq.x); fma2(g2[3][s], h0.y, pq.y);
            fma2(g2[4][s], h1.x, pq.x); fma2(g2[4][s], h1.y, pq.y);
            fma2(g2[5][s], h2.x, pq.x); fma2(g2[5][s], h2.y, pq.y);
        }
    }
    float bi0 = b_ih[d], bi1 = b_ih[64 + d], bi2 = b_ih[128 + d];
    float bh0 = b_hh[d], bh1 = b_hh[64 + d], bh2 = b_hh[128 + d];
    float h[7];
#pragma unroll
    for (int s = 0; s < 7; s++) {
        float2 t;
        t = up2(g2[0][s]); float gi0 = t.x + t.y + bi0;
        t = up2(g2[1][s]); float gi1 = t.x + t.y + bi1;
        t = up2(g2[2][s]); float gi2 = t.x + t.y + bi2;
        t = up2(g2[3][s]); float gh0 = t.x + t.y + bh0;
        t = up2(g2[4][s]); float gh1 = t.x + t.y + bh1;
        t = up2(g2[5][s]); float gh2 = t.x + t.y + bh2;
        float r = sigf(gi0 + gh0);
        float z = sigf(gi1 + gh1);
        float n = tanhf(gi2 + r * gh2);
        h[s] = (1.0f - z) * n + z * prev[s];
    }

    // ---- P3: LN(h) with ln_mlp ----
#pragma unroll
    for (int s = 0; s < 7; s++) {
        float s1 = h[s], s2 = h[s] * h[s];
#pragma unroll
        for (int off = 16; off; off >>= 1) {
            s1 += __shfl_xor_sync(0xffffffffu, s1, off);
            s2 += __shfl_xor_sync(0xffffffffu, s2, off);
        }
        if (lane == 0) { s_red[w][s][0] = s1; s_red[w][s][1] = s2; }
    }
    __syncthreads();
    float lgd = lmg[d], lbd = lmb[d];
#pragma unroll
    for (int s = 0; s < 7; s++) {
        float tot  = s_red[0][s][0] + s_red[1][s][0];
        float tot2 = s_red[0][s][1] + s_red[1][s][1];
        float mu = tot * (1.0f / 64.0f);
        float rs = rsqrtf(tot2 * (1.0f / 64.0f) - mu * mu + 1e-5f);
        sM_[s][d] = fmaf((h[s] - mu) * rs, lgd, lbd);
    }
    __syncthreads();

    // ---- P4: MLP layer 1 (64 -> 128, relu) ----
    ull ha[7], hb[7];
#pragma unroll
    for (int s = 0; s < 7; s++) { ha[s] = 0ull; hb[s] = 0ull; }
    const ulonglong2* w1a = (const ulonglong2*)(w1 + d * 64);
    const ulonglong2* w1b = (const ulonglong2*)(w1 + (64 + d) * 64);
#pragma unroll
    for (int i = 0; i < 16; i++) {
        ulonglong2 aa = w1a[i], bb = w1b[i];
#pragma unroll
        for (int s = 0; s < 7; s++) {
            ulonglong2 m = ((const ulonglong2*)sM_[s])[i];
            fma2(ha[s], aa.x, m.x); fma2(ha[s], aa.y, m.y);
            fma2(hb[s], bb.x, m.x); fma2(hb[s], bb.y, m.y);
        }
    }
    float b1a = b1p[d], b1b = b1p[64 + d];
#pragma unroll
    for (int s = 0; s < 7; s++) {
        float2 t = up2(ha[s]);
        sHid[s][d] = fmaxf(t.x + t.y + b1a, 0.f);
        t = up2(hb[s]);
        sHid[s][64 + d] = fmaxf(t.x + t.y + b1b, 0.f);
    }
    __syncthreads();

    // ---- P5: MLP layer 2 (128 -> 64) + residual ----
    ull mo2[7];
#pragma unroll
    for (int s = 0; s < 7; s++) mo2[s] = 0ull;
    const ulonglong2* w2r = (const ulonglong2*)(w2 + d * 128);
#pragma unroll
    for (int i = 0; i < 32; i++) {
        ulonglong2 aa = w2r[i];
#pragma unroll
        for (int s = 0; s < 7; s++) {
            ulonglong2 hh = ((const ulonglong2*)sHid[s])[i];
            fma2(mo2[s], aa.x, hh.x); fma2(mo2[s], aa.y, hh.y);
        }
    }
    float bb2 = b2p[d];
    float res[7];
#pragma unroll
    for (int s = 0; s < 7; s++) {
        float2 t = up2(mo2[s]);
        res[s] = h[s] + t.x + t.y + bb2;
        g_slots[b * SD + s * 64 + d] = res[s];
        if (last) out[b * SD + s * 64 + d] = res[s];
    }
    if (last) return;

    // ---- P6: qk for next iteration: LN(res, ln_slot) @ M ----
#pragma unroll
    for (int s = 0; s < 7; s++) {
        float s1 = res[s], s2 = res[s] * res[s];
#pragma unroll
        for (int off = 16; off; off >>= 1) {
            s1 += __shfl_xor_sync(0xffffffffu, s1, off);
            s2 += __shfl_xor_sync(0xffffffffu, s2, off);
        }
        if (lane == 0) { s_red[w][s][0] = s1; s_red[w][s][1] = s2; }
    }
    __syncthreads();
    float sgd = lsg[d], sbd = lsb[d];
#pragma unroll
    for (int s = 0; s < 7; s++) {
        float tot  = s_red[0][s][0] + s_red[1][s][0];
        float tot2 = s_red[0][s][1] + s_red[1][s][1];
        float mu = tot * (1.0f / 64.0f);
        float rs = rsqrtf(tot2 * (1.0f / 64.0f) - mu * mu + 1e-5f);
        sM_[s][d] = fmaf((res[s] - mu) * rs, sgd, sbd);
    }
    __syncthreads();

    float kacc[7];
#pragma unroll
    for (int s = 0; s < 7; s++) kacc[s] = 0.f;
#pragma unroll
    for (int i = 0; i < 16; i++) {
        float m0 = g_M[(4 * i + 0) * 64 + d], m1 = g_M[(4 * i + 1) * 64 + d];
        float m2 = g_M[(4 * i + 2) * 64 + d], m3 = g_M[(4 * i + 3) * 64 + d];
#pragma unroll
        for (int s = 0; s < 7; s++) {
            float4 x = ((const float4*)sM_[s])[i];
            kacc[s] = fmaf(x.x, m0, kacc[s]); kacc[s] = fmaf(x.y, m1, kacc[s]);
            kacc[s] = fmaf(x.z, m2, kacc[s]); kacc[s] = fmaf(x.w, m3, kacc[s]);
        }
    }
#pragma unroll
    for (int s = 0; s < 7; s++) g_qk[b * SD + s * 64 + d] = kacc[s];
}

extern "C" void kernel_launch(void* const* d_in, const int* in_sizes, int n_in,
                              void* d_out, int out_size) {
    const float* inputs = (const float*)d_in[0];
    const float* nbg    = (const float*)d_in[1];
    const float* nfg    = (const float*)d_in[2];
    const float* lin_g  = (const float*)d_in[3];
    const float* lin_b  = (const float*)d_in[4];
    const float* lsl_g  = (const float*)d_in[5];
    const float* lsl_b  = (const float*)d_in[6];
    const float* lml_g  = (const float*)d_in[7];
    const float* lml_b  = (const float*)d_in[8];
    const float* Wq     = (const float*)d_in[9];
    const float* Wk     = (const float*)d_in[10];
    const float* Wv     = (const float*)d_in[11];
    const float* W_ih   = (const float*)d_in[12];
    const float* W_hh   = (const float*)d_in[13];
    const float* b_ih   = (const float*)d_in[14];
    const float* b_hh   = (const float*)d_in[15];
    const float* w1     = (const float*)d_in[16];
    const float* b1     = (const float*)d_in[17];
    const float* w2     = (const float*)d_in[18];
    const float* b2     = (const float*)d_in[19];
    const float* bmu    = (const float*)d_in[20];
    const float* bls    = (const float*)d_in[21];
    const float* fmu    = (const float*)d_in[22];
    const float* fls    = (const float*)d_in[23];
    float* out = (float*)d_out;

    kprep<<<64, 64>>>(Wq, Wk);
    kinitq<<<BB, SD>>>(nbg, nfg, bmu, bls, fmu, fls, lsl_g, lsl_b);
    for (int it = 0; it < 3; it++) {
        dim3 ga(NCH, BB);
        kattn<<<ga, 256>>>(inputs, lin_g, lin_b);
        kupd<<<BB, 64>>>(Wv, W_ih, W_hh, b_ih, b_hh, w1, b1, w2, b2,
                         lml_g, lml_b, lsl_g, lsl_b, out, it == 2);
    }
}